// round 2
// baseline (speedup 1.0000x reference)
#include <cuda_runtime.h>
#include <cuda_bf16.h>
#include <cstddef>

// Problem constants
#define NB   64
#define NIC  128
#define NOC  256
#define NHW  56
#define NDG  4

// Tiling
#define OC_T 64      // output channels per block
#define SH   4       // output rows per block
#define SW   28      // output cols per block
#define ICC  8       // input-channel chunk
#define NTHREADS 224 // 8 oc-groups x 28 spatial threads

typedef unsigned long long u64;

// Premultiplied masked weights, layout [d][ic][tap][oc]  (oc contiguous)
__device__ float g_w[NDG * NIC * 9 * NOC];

// ---------------------------------------------------------------------------
// Packed f32x2 FMA (FFMA2) — 2 FMAs per instruction on sm_103a
// ---------------------------------------------------------------------------
__device__ __forceinline__ u64 ffma2(u64 a, u64 b, u64 c) {
    u64 d;
    asm("fma.rn.f32x2 %0, %1, %2, %3;" : "=l"(d) : "l"(a), "l"(b), "l"(c));
    return d;
}

// ---------------------------------------------------------------------------
// Prep: g_w[d][ic][tap][oc] = base[oc][ic][tap] * mask[d][ic][tap]
// ---------------------------------------------------------------------------
__global__ void prep_weights_kernel(const float* __restrict__ base,
                                    const float* __restrict__ mask) {
    int e = blockIdx.x * blockDim.x + threadIdx.x;
    const int total = NDG * NIC * 9 * NOC;
    if (e >= total) return;
    int oc  = e % NOC;
    int t2  = e / NOC;         // (d*128 + ic)*9 + tap
    int tap = t2 % 9;
    int t3  = t2 / 9;          // d*128 + ic
    int ic  = t3 % NIC;
    int d   = t3 / NIC;
    g_w[e] = base[(oc * NIC + ic) * 9 + tap] * mask[(d * NIC + ic) * 9 + tap];
}

// ---------------------------------------------------------------------------
// Direct tiled conv, fp32 via packed FFMA2.
// Block = (b, octile, spatial tile 4x28).
// Thread: ocg = tid%8 handles oc = ocg*8 .. ocg*8+7 (contiguous, as 4 pairs),
//         tw = tid/8 handles one w column, 4 h rows.
// Accumulators: acc[4 rows][4 oc-pairs] as packed f32x2 (32 floats).
// ---------------------------------------------------------------------------
__global__ __launch_bounds__(NTHREADS, 4)
void adaconv_kernel(const float* __restrict__ x,
                    const int*   __restrict__ label,
                    float*       __restrict__ out) {
    // x tile with value DUPLICATED in both lanes of a float2 -> one LDS.64
    // yields the broadcast operand for FFMA2 with zero register packing.
    __shared__ __align__(16) float2 xs2[ICC][SH + 2][32];   // 12 KB
    __shared__ __align__(16) float  ws[ICC][9][OC_T];       // 18 KB

    const int b      = blockIdx.z;
    const int octile = blockIdx.y;
    const int sp     = blockIdx.x;             // 0..27
    const int h0     = (sp >> 1) * SH;
    const int w0     = (sp & 1) * SW;

    const int tid = threadIdx.x;
    const int ocg = tid & 7;                   // 0..7
    const int tw  = tid >> 3;                  // 0..27

    int d = label[b];
    d = (d < 0) ? 0 : (d > NDG - 1 ? NDG - 1 : d);

    const float* __restrict__ wg = g_w + (size_t)d * NIC * 9 * NOC + octile * OC_T;
    const float* __restrict__ xg = x + (size_t)b * NIC * NHW * NHW;

    u64 acc[4][4];   // [row][oc-pair], each holds 2 packed fp32 accumulators
#pragma unroll
    for (int r = 0; r < 4; ++r)
#pragma unroll
        for (int p = 0; p < 4; ++p) acc[r][p] = 0ull;

    for (int icc = 0; icc < NIC / ICC; ++icc) {
        __syncthreads();

        // ---- load input patch: ICC x 6 x 30 (zero-padded halo), duplicated ----
        for (int idx = tid; idx < ICC * 6 * 30; idx += NTHREADS) {
            int ic  = idx / 180;
            int rem = idx % 180;
            int hh  = rem / 30;
            int ww  = rem % 30;
            int gh  = h0 - 1 + hh;
            int gw  = w0 - 1 + ww;
            float v = 0.f;
            if (gh >= 0 && gh < NHW && gw >= 0 && gw < NHW)
                v = xg[(icc * ICC + ic) * NHW * NHW + gh * NHW + gw];
            xs2[ic][hh][ww] = make_float2(v, v);
        }

        // ---- load weights: ws[ic][tap][oc], 256B-coalesced from g_w ----
        for (int idx = tid; idx < ICC * 9 * OC_T; idx += NTHREADS) {
            int oc  = idx & 63;
            int t2  = idx >> 6;
            int tap = t2 % 9;
            int ic  = t2 / 9;
            ws[ic][tap][oc] = wg[((icc * ICC + ic) * 9 + tap) * NOC + oc];
        }

        __syncthreads();

        // ---- compute: per (ic,tap): 4x LDS.64 (x pairs) + 2x LDS.128 (w) +
        //      16x FFMA2 -> fma-pipe-bound at 2 FMA/instr ----
#pragma unroll 2
        for (int ic = 0; ic < ICC; ++ic) {
#pragma unroll
            for (int kh = 0; kh < 3; ++kh) {
#pragma unroll
                for (int kw = 0; kw < 3; ++kw) {
                    // broadcast x pairs for the 4 output rows
                    u64 xv0 = *(const u64*)&xs2[ic][0 + kh][tw + kw];
                    u64 xv1 = *(const u64*)&xs2[ic][1 + kh][tw + kw];
                    u64 xv2 = *(const u64*)&xs2[ic][2 + kh][tw + kw];
                    u64 xv3 = *(const u64*)&xs2[ic][3 + kh][tw + kw];
                    // 8 contiguous weights = 4 packed pairs (2x LDS.128)
                    const float* wrow = &ws[ic][kh * 3 + kw][ocg * 8];
                    ulonglong2 wA = *(const ulonglong2*)&wrow[0];
                    ulonglong2 wB = *(const ulonglong2*)&wrow[4];

                    acc[0][0] = ffma2(xv0, wA.x, acc[0][0]);
                    acc[1][0] = ffma2(xv1, wA.x, acc[1][0]);
                    acc[2][0] = ffma2(xv2, wA.x, acc[2][0]);
                    acc[3][0] = ffma2(xv3, wA.x, acc[3][0]);

                    acc[0][1] = ffma2(xv0, wA.y, acc[0][1]);
                    acc[1][1] = ffma2(xv1, wA.y, acc[1][1]);
                    acc[2][1] = ffma2(xv2, wA.y, acc[2][1]);
                    acc[3][1] = ffma2(xv3, wA.y, acc[3][1]);

                    acc[0][2] = ffma2(xv0, wB.x, acc[0][2]);
                    acc[1][2] = ffma2(xv1, wB.x, acc[1][2]);
                    acc[2][2] = ffma2(xv2, wB.x, acc[2][2]);
                    acc[3][2] = ffma2(xv3, wB.x, acc[3][2]);

                    acc[0][3] = ffma2(xv0, wB.y, acc[0][3]);
                    acc[1][3] = ffma2(xv1, wB.y, acc[1][3]);
                    acc[2][3] = ffma2(xv2, wB.y, acc[2][3]);
                    acc[3][3] = ffma2(xv3, wB.y, acc[3][3]);
                }
            }
        }
    }

    // ---- write output: oc = octile*64 + ocg*8 + 2p (+1) ----
    float* __restrict__ og = out + ((size_t)b * NOC + octile * OC_T) * NHW * NHW
                                 + (size_t)(ocg * 8) * NHW * NHW;
#pragma unroll
    for (int p = 0; p < 4; ++p) {
#pragma unroll
        for (int r = 0; r < 4; ++r) {
            u64 v = acc[r][p];
            float lo = __uint_as_float((unsigned)(v & 0xFFFFFFFFull));
            float hi = __uint_as_float((unsigned)(v >> 32));
            size_t off = (size_t)(h0 + r) * NHW + (w0 + tw);
            og[(size_t)(2 * p)     * NHW * NHW + off] = lo;
            og[(size_t)(2 * p + 1) * NHW * NHW + off] = hi;
        }
    }
}

// ---------------------------------------------------------------------------
// Launch
// ---------------------------------------------------------------------------
extern "C" void kernel_launch(void* const* d_in, const int* in_sizes, int n_in,
                              void* d_out, int out_size) {
    const float* x     = nullptr;
    const int*   label = nullptr;
    const float* base  = nullptr;
    const float* mask  = nullptr;
    for (int i = 0; i < n_in; ++i) {
        switch (in_sizes[i]) {
            case 25690112: x     = (const float*)d_in[i]; break;
            case 64:       label = (const int*)  d_in[i]; break;
            case 294912:   base  = (const float*)d_in[i]; break;
            case 4608:     mask  = (const float*)d_in[i]; break;
            default: break; // epoch scalar etc.
        }
    }
    if (!x     && n_in > 0) x     = (const float*)d_in[0];
    if (!label && n_in > 1) label = (const int*)  d_in[1];
    if (!base  && n_in > 2) base  = (const float*)d_in[2];
    if (!mask  && n_in > 3) mask  = (const float*)d_in[3];

    float* out = (float*)d_out;

    {
        const int total = NDG * NIC * 9 * NOC;
        int threads = 256;
        int blocks  = (total + threads - 1) / threads;
        prep_weights_kernel<<<blocks, threads>>>(base, mask);
    }
    {
        dim3 grid(28, NOC / OC_T, NB);   // (spatial tiles, oc tiles, batch)
        adaconv_kernel<<<grid, NTHREADS>>>(x, label, out);
    }
}